// round 1
// baseline (speedup 1.0000x reference)
#include <cuda_runtime.h>

#define B_SZ   2
#define LQ     4096
#define LKV    1024
#define DMODEL 512
#define HEADS  8
#define DHEAD  64
#define SPAN   64
#define STRIDE 4
#define RWIN   16   // SPAN/STRIDE

// ---------------- scratch (no allocations allowed) ----------------
__device__ float g_Qp [B_SZ * LQ  * DMODEL];  // q @ Wq   [b, c, h*64+d]
__device__ float g_Kp [B_SZ * LKV * DMODEL];  // k @ Wk   [b, t, h*64+d]
__device__ float g_Vp [B_SZ * LKV * DMODEL];  // v @ Wv
__device__ float g_ctx[B_SZ * LQ  * DMODEL];  // attention output, pre out-proj

// ---------------- SGEMM: C[M,N] = A[M,K] * B[K,N], all row-major ----------------
// BM=128, BN=64, BK=16, 256 threads, 8x4 per-thread tile.
// M,N,K must be multiples of the tiles (true here: 8192/2048 x 512 x 512).
#define BM 128
#define BN 64
#define BK 16
#define TM 8
#define TN 4
#define APAD 4   // As stride 132: conflict-reduced scatter stores, keeps 16B alignment

__global__ __launch_bounds__(256) void sgemm_kernel(
    const float* __restrict__ A, const float* __restrict__ B,
    float* __restrict__ C, int M, int N, int K)
{
    __shared__ float As[BK][BM + APAD];   // transposed A tile
    __shared__ float Bs[BK][BN];

    const int tid  = threadIdx.x;
    const int tx   = tid % (BN / TN);     // 0..15 (n)
    const int ty   = tid / (BN / TN);     // 0..15 (m)
    const int row0 = blockIdx.y * BM;
    const int col0 = blockIdx.x * BN;

    float acc[TM][TN];
    #pragma unroll
    for (int i = 0; i < TM; i++)
        #pragma unroll
        for (int j = 0; j < TN; j++) acc[i][j] = 0.0f;

    for (int k0 = 0; k0 < K; k0 += BK) {
        // A tile: 128x16 = 2048 floats -> 2 float4 per thread, scatter-transpose
        #pragma unroll
        for (int i = 0; i < 2; i++) {
            int idx = tid + i * 256;          // 0..511
            int ar  = idx >> 2;               // 0..127
            int ac  = (idx & 3) << 2;         // 0,4,8,12
            float4 va = *(const float4*)&A[(size_t)(row0 + ar) * K + k0 + ac];
            As[ac + 0][ar] = va.x;
            As[ac + 1][ar] = va.y;
            As[ac + 2][ar] = va.z;
            As[ac + 3][ar] = va.w;
        }
        // B tile: 16x64 = 1024 floats -> 1 float4 per thread
        {
            int br = tid >> 4;                // 0..15
            int bc = (tid & 15) << 2;         // 0..60
            *(float4*)&Bs[br][bc] = *(const float4*)&B[(size_t)(k0 + br) * N + col0 + bc];
        }
        __syncthreads();

        #pragma unroll
        for (int kk = 0; kk < BK; kk++) {
            float ra[TM], rb[TN];
            *(float4*)&ra[0] = *(const float4*)&As[kk][ty * TM + 0];
            *(float4*)&ra[4] = *(const float4*)&As[kk][ty * TM + 4];
            *(float4*)&rb[0] = *(const float4*)&Bs[kk][tx * TN];
            #pragma unroll
            for (int i = 0; i < TM; i++)
                #pragma unroll
                for (int j = 0; j < TN; j++)
                    acc[i][j] = fmaf(ra[i], rb[j], acc[i][j]);
        }
        __syncthreads();
    }

    #pragma unroll
    for (int i = 0; i < TM; i++) {
        float4 v = make_float4(acc[i][0], acc[i][1], acc[i][2], acc[i][3]);
        *(float4*)&C[(size_t)(row0 + ty * TM + i) * N + col0 + tx * TN] = v;
    }
}

// ---------------- sparse sliding-window attention ----------------
// grid: (LQ/128, HEADS, B). block: 256 threads = 8 warps, warp -> 16 queries.
// For query c: qi_col(r) = r - floor((63-c)/4), qi_row = c - 4*qi_col,
// valid iff qi_row in [0,64) and qi_col in [0,1024).
#define QBLK 48   // max distinct KV rows touched by 128 consecutive queries (47)

__global__ __launch_bounds__(256) void sparse_attn_kernel(
    const float* __restrict__ Qp, const float* __restrict__ Kp,
    const float* __restrict__ Vp, float* __restrict__ ctx)
{
    __shared__ float Ks[QBLK][64];
    __shared__ float Vs[QBLK][64];

    const int c0 = blockIdx.x * 128;
    const int h  = blockIdx.y;
    const int b  = blockIdx.z;
    const int tid = threadIdx.x;

    // KV window for this block of 128 queries
    int jmin = (c0 - (SPAN - 1) + (STRIDE - 1)) >> 2;   // ceil((c0-63)/4)
    if (jmin < 0) jmin = 0;
    int jmax = (c0 + 127) >> 2;
    if (jmax > LKV - 1) jmax = LKV - 1;
    const int nrows = jmax - jmin + 1;                  // <= 47

    // cooperative load of K/V rows (64 floats each) into SMEM
    for (int idx = tid; idx < nrows * 16; idx += 256) {
        int rr = idx >> 4;
        int cc = (idx & 15) << 2;
        size_t src = (size_t)(b * LKV + jmin + rr) * DMODEL + h * DHEAD + cc;
        *(float4*)&Ks[rr][cc] = *(const float4*)&Kp[src];
        *(float4*)&Vs[rr][cc] = *(const float4*)&Vp[src];
    }
    __syncthreads();

    const int warp = tid >> 5;
    const int lane = tid & 31;

    for (int i = 0; i < 16; i++) {
        const int c = c0 + warp * 16 + i;
        const float* qptr = &Qp[(size_t)(b * LQ + c) * DMODEL + h * DHEAD];
        const float q0 = qptr[lane];
        const float q1 = qptr[lane + 32];

        const int f = (SPAN - 1 - c) >> 2;   // floor((63-c)/4), arithmetic shift

        float s[RWIN];
        #pragma unroll
        for (int r = 0; r < RWIN; r++) {
            const int jc = r - f;                 // qi_col
            const int qr = c - STRIDE * jc;       // qi_row
            const bool valid = (qr >= 0) && (qr < SPAN) && (jc >= 0) && (jc < LKV);
            if (valid) {
                const int rr = jc - jmin;
                float d = q0 * Ks[rr][lane] + q1 * Ks[rr][lane + 32];
                d += __shfl_xor_sync(0xffffffffu, d, 16);
                d += __shfl_xor_sync(0xffffffffu, d, 8);
                d += __shfl_xor_sync(0xffffffffu, d, 4);
                d += __shfl_xor_sync(0xffffffffu, d, 2);
                d += __shfl_xor_sync(0xffffffffu, d, 1);
                s[r] = d * 0.125f;                // / sqrt(64)
            } else {
                s[r] = -1e30f;
            }
        }

        float m = s[0];
        #pragma unroll
        for (int r = 1; r < RWIN; r++) m = fmaxf(m, s[r]);
        float denom = 0.0f;
        #pragma unroll
        for (int r = 0; r < RWIN; r++) { s[r] = __expf(s[r] - m); denom += s[r]; }
        const float inv = 1.0f / denom;           // >= 1 valid entry always exists

        float o0 = 0.0f, o1 = 0.0f;
        #pragma unroll
        for (int r = 0; r < RWIN; r++) {
            int rr = r - f - jmin;
            rr = max(0, min(rr, QBLK - 1));       // invalid entries have weight 0
            const float w = s[r] * inv;
            o0 = fmaf(w, Vs[rr][lane], o0);
            o1 = fmaf(w, Vs[rr][lane + 32], o1);
        }

        float* optr = &ctx[(size_t)(b * LQ + c) * DMODEL + h * DHEAD];
        optr[lane]      = o0;
        optr[lane + 32] = o1;
    }
}

// ---------------- launch ----------------
extern "C" void kernel_launch(void* const* d_in, const int* in_sizes, int n_in,
                              void* d_out, int out_size)
{
    const float* q    = (const float*)d_in[0];
    const float* k    = (const float*)d_in[1];
    const float* v    = (const float*)d_in[2];
    const float* Wq   = (const float*)d_in[3];
    const float* Wk   = (const float*)d_in[4];
    const float* Wv   = (const float*)d_in[5];
    const float* Wout = (const float*)d_in[6];
    float* out = (float*)d_out;

    float *Qp, *Kp, *Vp, *ctx;
    cudaGetSymbolAddress((void**)&Qp,  g_Qp);
    cudaGetSymbolAddress((void**)&Kp,  g_Kp);
    cudaGetSymbolAddress((void**)&Vp,  g_Vp);
    cudaGetSymbolAddress((void**)&ctx, g_ctx);

    const int MQ = B_SZ * LQ;    // 8192
    const int MK = B_SZ * LKV;   // 2048

    dim3 blk(256);
    // projections
    sgemm_kernel<<<dim3(DMODEL / BN, MQ / BM), blk>>>(q, Wq, Qp, MQ, DMODEL, DMODEL);
    sgemm_kernel<<<dim3(DMODEL / BN, MK / BM), blk>>>(k, Wk, Kp, MK, DMODEL, DMODEL);
    sgemm_kernel<<<dim3(DMODEL / BN, MK / BM), blk>>>(v, Wv, Vp, MK, DMODEL, DMODEL);
    // sparse attention
    sparse_attn_kernel<<<dim3(LQ / 128, HEADS, B_SZ), blk>>>(Qp, Kp, Vp, ctx);
    // output projection
    sgemm_kernel<<<dim3(DMODEL / BN, MQ / BM), blk>>>(ctx, Wout, out, MQ, DMODEL, DMODEL);
}

// round 2
// speedup vs baseline: 1.4002x; 1.4002x over previous
#include <cuda_runtime.h>

#define B_SZ   2
#define LQ     4096
#define LKV    1024
#define DMODEL 512
#define HEADS  8
#define DHEAD  64
#define SPAN   64
#define STRIDE 4
#define RWIN   16

// ---------------- scratch ----------------
__device__ float g_Qp [B_SZ * LQ  * DMODEL];
__device__ float g_Kp [B_SZ * LKV * DMODEL];
__device__ float g_Vp [B_SZ * LKV * DMODEL];
__device__ float g_ctx[B_SZ * LQ  * DMODEL];

// ---------------- packed fp32 helpers ----------------
__device__ __forceinline__ unsigned long long f32x2_fma(
    unsigned long long a, unsigned long long b, unsigned long long c)
{
    unsigned long long d;
    asm("fma.rn.f32x2 %0, %1, %2, %3;" : "=l"(d) : "l"(a), "l"(b), "l"(c));
    return d;
}
__device__ __forceinline__ unsigned long long f32_bcast2(float x)
{
    unsigned long long d;
    asm("mov.b64 %0, {%1, %1};" : "=l"(d) : "f"(x));
    return d;
}
__device__ __forceinline__ float2 f32x2_unpack(unsigned long long v)
{
    float2 r;
    asm("mov.b64 {%0, %1}, %2;" : "=f"(r.x), "=f"(r.y) : "l"(v));
    return r;
}

// ---------------- 128x128x512 GEMM tile (N=K=512 fixed) ----------------
// 256 threads, per-thread 8x8 via fma.rn.f32x2 (32 FFMA2 / k-step).
#define GBM 128
#define GBN 128
#define GBK 16
#define APAD 4

__device__ __forceinline__ void gemm_tile_128(
    const float* __restrict__ A, const float* __restrict__ B,
    float* __restrict__ C, int row0, int col0)
{
    __shared__ float As[GBK][GBM + APAD];
    __shared__ float Bs[GBK][GBN];

    const int tid = threadIdx.x;
    const int tx  = tid & 15;    // n: 16 x 8 = 128
    const int ty  = tid >> 4;    // m: 16 x 8 = 128

    unsigned long long acc[8][4];
    #pragma unroll
    for (int i = 0; i < 8; i++)
        #pragma unroll
        for (int j = 0; j < 4; j++) acc[i][j] = 0ULL;

    for (int k0 = 0; k0 < DMODEL; k0 += GBK) {
        // A tile: 128x16, scatter-transpose. 2 float4 / thread.
        #pragma unroll
        for (int i = 0; i < 2; i++) {
            int idx = tid + i * 256;            // 0..511
            int ar  = idx >> 2;
            int ac  = (idx & 3) << 2;
            float4 va = *(const float4*)&A[(size_t)(row0 + ar) * DMODEL + k0 + ac];
            As[ac + 0][ar] = va.x;
            As[ac + 1][ar] = va.y;
            As[ac + 2][ar] = va.z;
            As[ac + 3][ar] = va.w;
        }
        // B tile: 16x128. 2 float4 / thread.
        #pragma unroll
        for (int i = 0; i < 2; i++) {
            int idx = tid + i * 256;
            int br  = idx >> 5;
            int bc  = (idx & 31) << 2;
            *(float4*)&Bs[br][bc] = *(const float4*)&B[(size_t)(k0 + br) * DMODEL + col0 + bc];
        }
        __syncthreads();

        #pragma unroll
        for (int kk = 0; kk < GBK; kk++) {
            float4 a0 = *(const float4*)&As[kk][ty * 8 + 0];
            float4 a1 = *(const float4*)&As[kk][ty * 8 + 4];
            ulonglong2 b01 = *(const ulonglong2*)&Bs[kk][tx * 8 + 0];
            ulonglong2 b23 = *(const ulonglong2*)&Bs[kk][tx * 8 + 4];

            float ra[8] = {a0.x, a0.y, a0.z, a0.w, a1.x, a1.y, a1.z, a1.w};
            unsigned long long rb[4] = {b01.x, b01.y, b23.x, b23.y};

            #pragma unroll
            for (int i = 0; i < 8; i++) {
                unsigned long long aa = f32_bcast2(ra[i]);
                #pragma unroll
                for (int j = 0; j < 4; j++)
                    acc[i][j] = f32x2_fma(aa, rb[j], acc[i][j]);
            }
        }
        __syncthreads();
    }

    #pragma unroll
    for (int i = 0; i < 8; i++) {
        float2 p0 = f32x2_unpack(acc[i][0]);
        float2 p1 = f32x2_unpack(acc[i][1]);
        float2 p2 = f32x2_unpack(acc[i][2]);
        float2 p3 = f32x2_unpack(acc[i][3]);
        float* cp = &C[(size_t)(row0 + ty * 8 + i) * DMODEL + col0 + tx * 8];
        *(float4*)&cp[0] = make_float4(p0.x, p0.y, p1.x, p1.y);
        *(float4*)&cp[4] = make_float4(p2.x, p2.y, p3.x, p3.y);
    }
}

// Fused Q/K/V projections: 256 + 64 + 64 = 384 blocks in one launch.
__global__ __launch_bounds__(256, 2) void proj_fused_kernel(
    const float* __restrict__ q, const float* __restrict__ Wq, float* __restrict__ Qp,
    const float* __restrict__ k, const float* __restrict__ Wk, float* __restrict__ Kp,
    const float* __restrict__ v, const float* __restrict__ Wv, float* __restrict__ Vp)
{
    int bid = blockIdx.x;
    const float *A, *B; float* C; int t;
    if (bid < 256)      { A = q; B = Wq; C = Qp; t = bid; }
    else if (bid < 320) { A = k; B = Wk; C = Kp; t = bid - 256; }
    else                { A = v; B = Wv; C = Vp; t = bid - 320; }
    gemm_tile_128(A, B, C, (t >> 2) * GBM, (t & 3) * GBN);
}

__global__ __launch_bounds__(256, 2) void gemm_single_kernel(
    const float* __restrict__ A, const float* __restrict__ B, float* __restrict__ C)
{
    gemm_tile_128(A, B, C, blockIdx.y * GBM, blockIdx.x * GBN);
}

// ---------------- sparse attention: one lane = one query ----------------
// Block: 128 threads = 128 queries for one (b,h). No shuffles; scores,
// softmax, weights all in per-lane registers. K/V in SMEM, pad-68 rows.
#define QBLK 48
#define KVPAD 68

__global__ __launch_bounds__(128) void sparse_attn_kernel(
    const float* __restrict__ Qp, const float* __restrict__ Kp,
    const float* __restrict__ Vp, float* __restrict__ ctx)
{
    __shared__ float Ks[QBLK][KVPAD];
    __shared__ float Vs[QBLK][KVPAD];

    const int c0  = blockIdx.x * 128;
    const int h   = blockIdx.y;
    const int b   = blockIdx.z;
    const int tid = threadIdx.x;

    int jmin = (c0 - (SPAN - 1) + (STRIDE - 1)) >> 2;
    if (jmin < 0) jmin = 0;
    int jmax = (c0 + 127) >> 2;
    if (jmax > LKV - 1) jmax = LKV - 1;
    const int nrows = jmax - jmin + 1;            // <= 47

    for (int idx = tid; idx < nrows * 16; idx += 128) {
        int rr = idx >> 4;
        int cc = (idx & 15) << 2;
        size_t src = (size_t)(b * LKV + jmin + rr) * DMODEL + h * DHEAD + cc;
        *(float4*)&Ks[rr][cc] = *(const float4*)&Kp[src];
        *(float4*)&Vs[rr][cc] = *(const float4*)&Vp[src];
    }
    __syncthreads();

    const int c = c0 + tid;
    const int f = (SPAN - 1 - c) >> 2;            // floor((63-c)/4)

    // per-r row index (clamped) + validity
    int  rrc[RWIN];
    bool vld[RWIN];
    #pragma unroll
    for (int r = 0; r < RWIN; r++) {
        int jc = r - f;
        int qr = c - STRIDE * jc;
        vld[r] = (qr >= 0) && (qr < SPAN) && (jc >= 0) && (jc < LKV);
        int rr = jc - jmin;
        rrc[r] = max(0, min(rr, QBLK - 1));
    }

    // scores: loop head-dim in float4 chunks, q from global (L2-hot)
    const float* qptr = &Qp[(size_t)(b * LQ + c) * DMODEL + h * DHEAD];
    float s[RWIN];
    #pragma unroll
    for (int r = 0; r < RWIN; r++) s[r] = 0.0f;
    #pragma unroll
    for (int d0 = 0; d0 < DHEAD; d0 += 4) {
        float4 q4 = *(const float4*)&qptr[d0];
        #pragma unroll
        for (int r = 0; r < RWIN; r++) {
            float4 k4 = *(const float4*)&Ks[rrc[r]][d0];
            float t = s[r];
            t = fmaf(q4.x, k4.x, t);
            t = fmaf(q4.y, k4.y, t);
            t = fmaf(q4.z, k4.z, t);
            t = fmaf(q4.w, k4.w, t);
            s[r] = t;
        }
    }

    // softmax (per-lane, register-resident)
    float m = -1e30f;
    #pragma unroll
    for (int r = 0; r < RWIN; r++) {
        s[r] = vld[r] ? s[r] * 0.125f : -1e30f;
        m = fmaxf(m, s[r]);
    }
    float denom = 0.0f;
    float w[RWIN];
    #pragma unroll
    for (int r = 0; r < RWIN; r++) { w[r] = __expf(s[r] - m); denom += w[r]; }
    const float inv = 1.0f / denom;
    #pragma unroll
    for (int r = 0; r < RWIN; r++) w[r] = vld[r] ? w[r] * inv : 0.0f;

    // output: d-chunk outer, r inner; only a float4 of o live at a time
    float* optr = &ctx[(size_t)(b * LQ + c) * DMODEL + h * DHEAD];
    #pragma unroll
    for (int d0 = 0; d0 < DHEAD; d0 += 4) {
        float4 o = make_float4(0.f, 0.f, 0.f, 0.f);
        #pragma unroll
        for (int r = 0; r < RWIN; r++) {
            float4 v4 = *(const float4*)&Vs[rrc[r]][d0];
            o.x = fmaf(w[r], v4.x, o.x);
            o.y = fmaf(w[r], v4.y, o.y);
            o.z = fmaf(w[r], v4.z, o.z);
            o.w = fmaf(w[r], v4.w, o.w);
        }
        *(float4*)&optr[d0] = o;
    }
}

// ---------------- launch ----------------
extern "C" void kernel_launch(void* const* d_in, const int* in_sizes, int n_in,
                              void* d_out, int out_size)
{
    const float* q    = (const float*)d_in[0];
    const float* k    = (const float*)d_in[1];
    const float* v    = (const float*)d_in[2];
    const float* Wq   = (const float*)d_in[3];
    const float* Wk   = (const float*)d_in[4];
    const float* Wv   = (const float*)d_in[5];
    const float* Wout = (const float*)d_in[6];
    float* out = (float*)d_out;

    float *Qp, *Kp, *Vp, *ctx;
    cudaGetSymbolAddress((void**)&Qp,  g_Qp);
    cudaGetSymbolAddress((void**)&Kp,  g_Kp);
    cudaGetSymbolAddress((void**)&Vp,  g_Vp);
    cudaGetSymbolAddress((void**)&ctx, g_ctx);

    proj_fused_kernel<<<384, 256>>>(q, Wq, Qp, k, Wk, Kp, v, Wv, Vp);
    sparse_attn_kernel<<<dim3(LQ / 128, HEADS, B_SZ), 128>>>(Qp, Kp, Vp, ctx);
    gemm_single_kernel<<<dim3(4, 64), 256>>>(ctx, Wout, out);
}

// round 4
// speedup vs baseline: 2.3490x; 1.6776x over previous
#include <cuda_runtime.h>
#include <cuda_bf16.h>
#include <cstdint>

#define B_SZ   2
#define LQ     4096
#define LKV    1024
#define DMODEL 512
#define HEADS  8
#define DHEAD  64
#define SPAN   64
#define STRIDE 4
#define RWIN   16

#define MQ (B_SZ * LQ)    // 8192
#define MK (B_SZ * LKV)   // 2048

// ---------------- scratch ----------------
__device__ float g_Qp [MQ * DMODEL];
__device__ float g_Kp [MK * DMODEL];
__device__ float g_Vp [MK * DMODEL];
__device__ __nv_bfloat16 g_qh[MQ * DMODEL], g_ql[MQ * DMODEL];
__device__ __nv_bfloat16 g_kh[MK * DMODEL], g_kl[MK * DMODEL];
__device__ __nv_bfloat16 g_vh[MK * DMODEL], g_vl[MK * DMODEL];
__device__ __nv_bfloat16 g_ch[MQ * DMODEL], g_cl[MQ * DMODEL];
__device__ __nv_bfloat16 g_Wth[4 * DMODEL * DMODEL], g_Wtl[4 * DMODEL * DMODEL];

// ---------------- helpers ----------------
__device__ __forceinline__ uint32_t smem_u32(const void* p) {
    uint32_t a;
    asm("{ .reg .u64 t; cvta.to.shared.u64 t, %1; cvt.u32.u64 %0, t; }" : "=r"(a) : "l"(p));
    return a;
}
__device__ __forceinline__ void bf16_split(float x, __nv_bfloat16& h, __nv_bfloat16& l) {
    h = __float2bfloat16_rn(x);
    l = __float2bfloat16_rn(x - __bfloat162float(h));
}
__device__ __forceinline__ void ldsm_x4(uint32_t* r, uint32_t a) {
    asm volatile("ldmatrix.sync.aligned.m8n8.x4.shared.b16 {%0,%1,%2,%3}, [%4];"
        : "=r"(r[0]), "=r"(r[1]), "=r"(r[2]), "=r"(r[3]) : "r"(a));
}
__device__ __forceinline__ void ldsm_x2(uint32_t* r, uint32_t a) {
    asm volatile("ldmatrix.sync.aligned.m8n8.x2.shared.b16 {%0,%1}, [%2];"
        : "=r"(r[0]), "=r"(r[1]) : "r"(a));
}
__device__ __forceinline__ void mma_bf16(float* c, const uint32_t* a, const uint32_t* b) {
    asm volatile(
        "mma.sync.aligned.m16n8k16.row.col.f32.bf16.bf16.f32 "
        "{%0,%1,%2,%3}, {%4,%5,%6,%7}, {%8,%9}, {%0,%1,%2,%3};"
        : "+f"(c[0]), "+f"(c[1]), "+f"(c[2]), "+f"(c[3])
        : "r"(a[0]), "r"(a[1]), "r"(a[2]), "r"(a[3]), "r"(b[0]), "r"(b[1]));
}

// ---------------- prepass: split activations into bf16 hi/lo ----------------
__global__ __launch_bounds__(256) void split_act_kernel(
    const float* __restrict__ q, const float* __restrict__ k, const float* __restrict__ v,
    __nv_bfloat16* __restrict__ qh, __nv_bfloat16* __restrict__ ql,
    __nv_bfloat16* __restrict__ kh, __nv_bfloat16* __restrict__ kl,
    __nv_bfloat16* __restrict__ vh, __nv_bfloat16* __restrict__ vl)
{
    const int QE = MQ * DMODEL / 4;     // float4 count
    const int KE = MK * DMODEL / 4;
    int i = blockIdx.x * blockDim.x + threadIdx.x;
    const float* src; __nv_bfloat16 *dh, *dl;
    if (i < QE)                { src = q; dh = qh; dl = ql; }
    else if (i < QE + KE)      { src = k; dh = kh; dl = kl; i -= QE; }
    else if (i < QE + 2 * KE)  { src = v; dh = vh; dl = vl; i -= QE + KE; }
    else return;
    float4 x = ((const float4*)src)[i];
    __nv_bfloat16 h0, h1, h2, h3, l0, l1, l2, l3;
    bf16_split(x.x, h0, l0); bf16_split(x.y, h1, l1);
    bf16_split(x.z, h2, l2); bf16_split(x.w, h3, l3);
    ((__nv_bfloat162*)dh)[i * 2 + 0] = __nv_bfloat162(h0, h1);
    ((__nv_bfloat162*)dh)[i * 2 + 1] = __nv_bfloat162(h2, h3);
    ((__nv_bfloat162*)dl)[i * 2 + 0] = __nv_bfloat162(l0, l1);
    ((__nv_bfloat162*)dl)[i * 2 + 1] = __nv_bfloat162(l2, l3);
}

// ---------------- prepass: transpose + split weights ----------------
__global__ __launch_bounds__(1024) void split_w_kernel(
    const float* __restrict__ W0, const float* __restrict__ W1,
    const float* __restrict__ W2, const float* __restrict__ W3,
    __nv_bfloat16* __restrict__ Wth, __nv_bfloat16* __restrict__ Wtl)
{
    __shared__ float t[32][33];
    const int z = blockIdx.z;
    const float* W = (z == 0) ? W0 : (z == 1) ? W1 : (z == 2) ? W2 : W3;
    const int n0 = blockIdx.x * 32, k0 = blockIdx.y * 32;
    const int tx = threadIdx.x, ty = threadIdx.y;
    t[ty][tx] = W[(size_t)(k0 + ty) * DMODEL + n0 + tx];
    __syncthreads();
    float x = t[tx][ty];
    __nv_bfloat16 h, l;
    bf16_split(x, h, l);
    size_t o = (size_t)z * DMODEL * DMODEL + (size_t)(n0 + ty) * DMODEL + k0 + tx;
    Wth[o] = h; Wtl[o] = l;
}

// ---------------- bf16x3 GEMM tile: C[128,128] fp32 = A[128,512] @ Bt[128,512]^T --------
// smem: 4 tiles of 128 rows x 64 bf16, padded rows 72 bf16 (144B)
#define ROWB 144
#define SA_H 0
#define SA_L 18432
#define SB_H 36864
#define SB_L 55296
#define SM_GEMM_TOTAL 73728
#define NCHUNK 8   // 512 / 64

__device__ __forceinline__ void gemm_bf16x3_tile(
    const __nv_bfloat16* __restrict__ Ah, const __nv_bfloat16* __restrict__ Al,
    const __nv_bfloat16* __restrict__ Bh, const __nv_bfloat16* __restrict__ Bl,
    float* __restrict__ C, int row0, int col0)
{
    extern __shared__ char sm[];
    const uint32_t sb = smem_u32(sm);
    const int tid  = threadIdx.x;
    const int wid  = tid >> 5;
    const int lane = tid & 31;
    const int m0 = (wid & 1) * 64;     // warp row base in tile
    const int n0 = (wid >> 1) * 32;    // warp col base in tile

    float acc[4][4][4];
    #pragma unroll
    for (int mi = 0; mi < 4; mi++)
        #pragma unroll
        for (int ni = 0; ni < 4; ni++)
            #pragma unroll
            for (int e = 0; e < 4; e++) acc[mi][ni][e] = 0.0f;

    // per-lane ldmatrix address bases (byte offsets within a tile)
    const uint32_t a_base = (uint32_t)(m0 + (lane & 15)) * ROWB + ((lane >> 4) << 4);
    const uint32_t b_base = (uint32_t)(n0 + (lane & 7)) * ROWB + (((lane >> 3) & 1) << 4);

    for (int ch = 0; ch < NCHUNK; ch++) {
        const int k0 = ch * 64;
        __syncthreads();   // previous chunk's MMAs done reading smem
        #pragma unroll
        for (int j = 0; j < 4; j++) {
            int idx = tid + j * 256;        // 0..1023
            int r   = idx >> 3;             // 0..127
            int cb  = (idx & 7) << 4;       // byte col 0..112
            uint32_t so = (uint32_t)r * ROWB + cb;
            size_t ga = ((size_t)(row0 + r) * DMODEL + k0) * 2 + cb;
            size_t gb = ((size_t)(col0 + r) * DMODEL + k0) * 2 + cb;
            *(uint4*)(sm + SA_H + so) = *(const uint4*)((const char*)Ah + ga);
            *(uint4*)(sm + SA_L + so) = *(const uint4*)((const char*)Al + ga);
            *(uint4*)(sm + SB_H + so) = *(const uint4*)((const char*)Bh + gb);
            *(uint4*)(sm + SB_L + so) = *(const uint4*)((const char*)Bl + gb);
        }
        __syncthreads();

        #pragma unroll
        for (int ks = 0; ks < 4; ks++) {
            const uint32_t ko = (uint32_t)ks * 32;   // 16 bf16 = 32B per k-step
            uint32_t ah[4][4], al[4][4], bh[4][2], bl[4][2];
            #pragma unroll
            for (int mi = 0; mi < 4; mi++) {
                uint32_t ao = a_base + (uint32_t)(mi * 16) * ROWB + ko;
                ldsm_x4(ah[mi], sb + SA_H + ao);
                ldsm_x4(al[mi], sb + SA_L + ao);
            }
            #pragma unroll
            for (int ni = 0; ni < 4; ni++) {
                uint32_t bo = b_base + (uint32_t)(ni * 8) * ROWB + ko;
                ldsm_x2(bh[ni], sb + SB_H + bo);
                ldsm_x2(bl[ni], sb + SB_L + bo);
            }
            #pragma unroll
            for (int mi = 0; mi < 4; mi++)
                #pragma unroll
                for (int ni = 0; ni < 4; ni++) {
                    mma_bf16(acc[mi][ni], ah[mi], bh[ni]);
                    mma_bf16(acc[mi][ni], ah[mi], bl[ni]);
                    mma_bf16(acc[mi][ni], al[mi], bh[ni]);
                }
        }
    }

    // epilogue
    #pragma unroll
    for (int mi = 0; mi < 4; mi++) {
        #pragma unroll
        for (int ni = 0; ni < 4; ni++) {
            int row = row0 + m0 + mi * 16 + (lane >> 2);
            int col = col0 + n0 + ni * 8 + (lane & 3) * 2;
            *(float2*)&C[(size_t)row * DMODEL + col] =
                make_float2(acc[mi][ni][0], acc[mi][ni][1]);
            *(float2*)&C[(size_t)(row + 8) * DMODEL + col] =
                make_float2(acc[mi][ni][2], acc[mi][ni][3]);
        }
    }
}

// fused Q/K/V projections: 256 + 64 + 64 = 384 CTAs
__global__ __launch_bounds__(256) void proj_fused_kernel(
    const __nv_bfloat16* __restrict__ qh, const __nv_bfloat16* __restrict__ ql,
    const __nv_bfloat16* __restrict__ kh, const __nv_bfloat16* __restrict__ kl,
    const __nv_bfloat16* __restrict__ vh, const __nv_bfloat16* __restrict__ vl,
    const __nv_bfloat16* __restrict__ Wth, const __nv_bfloat16* __restrict__ Wtl,
    float* __restrict__ Qp, float* __restrict__ Kp, float* __restrict__ Vp)
{
    const int bid = blockIdx.x;
    const size_t WSZ = (size_t)DMODEL * DMODEL;
    const __nv_bfloat16 *Ah, *Al, *Bh, *Bl; float* C; int t;
    if (bid < 256)      { Ah = qh; Al = ql; Bh = Wth;           Bl = Wtl;           C = Qp; t = bid; }
    else if (bid < 320) { Ah = kh; Al = kl; Bh = Wth + WSZ;     Bl = Wtl + WSZ;     C = Kp; t = bid - 256; }
    else                { Ah = vh; Al = vl; Bh = Wth + 2 * WSZ; Bl = Wtl + 2 * WSZ; C = Vp; t = bid - 320; }
    gemm_bf16x3_tile(Ah, Al, Bh, Bl, C, (t >> 2) * 128, (t & 3) * 128);
}

__global__ __launch_bounds__(256) void outproj_kernel(
    const __nv_bfloat16* __restrict__ ch, const __nv_bfloat16* __restrict__ cl,
    const __nv_bfloat16* __restrict__ Wth, const __nv_bfloat16* __restrict__ Wtl,
    float* __restrict__ out)
{
    const size_t WSZ = (size_t)DMODEL * DMODEL;
    gemm_bf16x3_tile(ch, cl, Wth + 3 * WSZ, Wtl + 3 * WSZ, out,
                     blockIdx.y * 128, blockIdx.x * 128);
}

// ---------------- sparse attention (fp32 math, bf16 hi/lo output) ----------------
#define QBLK 48
#define KVPAD 68

__global__ __launch_bounds__(128) void sparse_attn_kernel(
    const float* __restrict__ Qp, const float* __restrict__ Kp,
    const float* __restrict__ Vp,
    __nv_bfloat16* __restrict__ ctxh, __nv_bfloat16* __restrict__ ctxl)
{
    __shared__ float Ks[QBLK][KVPAD];
    __shared__ float Vs[QBLK][KVPAD];

    const int c0  = blockIdx.x * 128;
    const int h   = blockIdx.y;
    const int b   = blockIdx.z;
    const int tid = threadIdx.x;

    int jmin = (c0 - (SPAN - 1) + (STRIDE - 1)) >> 2;
    if (jmin < 0) jmin = 0;
    int jmax = (c0 + 127) >> 2;
    if (jmax > LKV - 1) jmax = LKV - 1;
    const int nrows = jmax - jmin + 1;

    for (int idx = tid; idx < nrows * 16; idx += 128) {
        int rr = idx >> 4;
        int cc = (idx & 15) << 2;
        size_t src = (size_t)(b * LKV + jmin + rr) * DMODEL + h * DHEAD + cc;
        *(float4*)&Ks[rr][cc] = *(const float4*)&Kp[src];
        *(float4*)&Vs[rr][cc] = *(const float4*)&Vp[src];
    }
    __syncthreads();

    const int c = c0 + tid;
    const int f = (SPAN - 1 - c) >> 2;

    int  rrc[RWIN];
    bool vld[RWIN];
    #pragma unroll
    for (int r = 0; r < RWIN; r++) {
        int jc = r - f;
        int qr = c - STRIDE * jc;
        vld[r] = (qr >= 0) && (qr < SPAN) && (jc >= 0) && (jc < LKV);
        int rr = jc - jmin;
        rrc[r] = max(0, min(rr, QBLK - 1));
    }

    const float* qptr = &Qp[(size_t)(b * LQ + c) * DMODEL + h * DHEAD];
    float s[RWIN];
    #pragma unroll
    for (int r = 0; r < RWIN; r++) s[r] = 0.0f;
    #pragma unroll
    for (int d0 = 0; d0 < DHEAD; d0 += 4) {
        float4 q4 = *(const float4*)&qptr[d0];
        #pragma unroll
        for (int r = 0; r < RWIN; r++) {
            float4 k4 = *(const float4*)&Ks[rrc[r]][d0];
            float t = s[r];
            t = fmaf(q4.x, k4.x, t);
            t = fmaf(q4.y, k4.y, t);
            t = fmaf(q4.z, k4.z, t);
            t = fmaf(q4.w, k4.w, t);
            s[r] = t;
        }
    }

    float m = -1e30f;
    #pragma unroll
    for (int r = 0; r < RWIN; r++) {
        s[r] = vld[r] ? s[r] * 0.125f : -1e30f;
        m = fmaxf(m, s[r]);
    }
    float denom = 0.0f;
    float w[RWIN];
    #pragma unroll
    for (int r = 0; r < RWIN; r++) { w[r] = __expf(s[r] - m); denom += w[r]; }
    const float inv = 1.0f / denom;
    #pragma unroll
    for (int r = 0; r < RWIN; r++) w[r] = vld[r] ? w[r] * inv : 0.0f;

    const size_t obase = (size_t)(b * LQ + c) * DMODEL + h * DHEAD;
    #pragma unroll
    for (int d0 = 0; d0 < DHEAD; d0 += 4) {
        float4 o = make_float4(0.f, 0.f, 0.f, 0.f);
        #pragma unroll
        for (int r = 0; r < RWIN; r++) {
            float4 v4 = *(const float4*)&Vs[rrc[r]][d0];
            o.x = fmaf(w[r], v4.x, o.x);
            o.y = fmaf(w[r], v4.y, o.y);
            o.z = fmaf(w[r], v4.z, o.z);
            o.w = fmaf(w[r], v4.w, o.w);
        }
        __nv_bfloat16 h0, h1, h2, h3, l0, l1, l2, l3;
        bf16_split(o.x, h0, l0); bf16_split(o.y, h1, l1);
        bf16_split(o.z, h2, l2); bf16_split(o.w, h3, l3);
        *(__nv_bfloat162*)&ctxh[obase + d0]     = __nv_bfloat162(h0, h1);
        *(__nv_bfloat162*)&ctxh[obase + d0 + 2] = __nv_bfloat162(h2, h3);
        *(__nv_bfloat162*)&ctxl[obase + d0]     = __nv_bfloat162(l0, l1);
        *(__nv_bfloat162*)&ctxl[obase + d0 + 2] = __nv_bfloat162(l2, l3);
    }
}

// ---------------- launch ----------------
extern "C" void kernel_launch(void* const* d_in, const int* in_sizes, int n_in,
                              void* d_out, int out_size)
{
    const float* q    = (const float*)d_in[0];
    const float* k    = (const float*)d_in[1];
    const float* v    = (const float*)d_in[2];
    const float* Wq   = (const float*)d_in[3];
    const float* Wk   = (const float*)d_in[4];
    const float* Wv   = (const float*)d_in[5];
    const float* Wout = (const float*)d_in[6];
    float* out = (float*)d_out;

    float *Qp, *Kp, *Vp;
    __nv_bfloat16 *qh, *ql, *kh, *kl, *vh, *vl, *ch, *cl, *Wth, *Wtl;
    cudaGetSymbolAddress((void**)&Qp,  g_Qp);
    cudaGetSymbolAddress((void**)&Kp,  g_Kp);
    cudaGetSymbolAddress((void**)&Vp,  g_Vp);
    cudaGetSymbolAddress((void**)&qh,  g_qh);  cudaGetSymbolAddress((void**)&ql, g_ql);
    cudaGetSymbolAddress((void**)&kh,  g_kh);  cudaGetSymbolAddress((void**)&kl, g_kl);
    cudaGetSymbolAddress((void**)&vh,  g_vh);  cudaGetSymbolAddress((void**)&vl, g_vl);
    cudaGetSymbolAddress((void**)&ch,  g_ch);  cudaGetSymbolAddress((void**)&cl, g_cl);
    cudaGetSymbolAddress((void**)&Wth, g_Wth); cudaGetSymbolAddress((void**)&Wtl, g_Wtl);

    cudaFuncSetAttribute(proj_fused_kernel,
                         cudaFuncAttributeMaxDynamicSharedMemorySize, SM_GEMM_TOTAL);
    cudaFuncSetAttribute(outproj_kernel,
                         cudaFuncAttributeMaxDynamicSharedMemorySize, SM_GEMM_TOTAL);

    // 1) split activations + weights into bf16 hi/lo (weights transposed)
    const int totalV = (MQ * DMODEL + 2 * MK * DMODEL) / 4;
    split_act_kernel<<<(totalV + 255) / 256, 256>>>(q, k, v, qh, ql, kh, kl, vh, vl);
    split_w_kernel<<<dim3(16, 16, 4), dim3(32, 32)>>>(Wq, Wk, Wv, Wout, Wth, Wtl);
    // 2) Q/K/V projections (bf16x3 on tensor cores)
    proj_fused_kernel<<<384, 256, SM_GEMM_TOTAL>>>(qh, ql, kh, kl, vh, vl, Wth, Wtl, Qp, Kp, Vp);
    // 3) sparse attention (emits ctx as bf16 hi/lo)
    sparse_attn_kernel<<<dim3(LQ / 128, HEADS, B_SZ), 128>>>(Qp, Kp, Vp, ch, cl);
    // 4) output projection
    outproj_kernel<<<dim3(4, 64), 256, SM_GEMM_TOTAL>>>(ch, cl, Wth, Wtl, out);
}